// round 1
// baseline (speedup 1.0000x reference)
#include <cuda_runtime.h>
#include <math.h>

#define DIM   4096
#define NH    32
#define HD    128
#define BSZ   2
#define SEQ   2048
#define MTOT  (BSZ*SEQ)     // 4096 rows for the big GEMMs

// Scratch (allocation-free rule: __device__ globals)
__device__ float g_q[BSZ*SEQ*DIM];     // 64 MiB
__device__ float g_k[BSZ*SEQ*DIM];
__device__ float g_v[BSZ*SEQ*DIM];
__device__ float g_attn[BSZ*SEQ*DIM];
__device__ float g_cos[SEQ*(HD/2)];
__device__ float g_sin[SEQ*(HD/2)];

// ---------------------------------------------------------------------------
// GEMM: C[m,n] = sum_k A[m,k] * W[n,k]   (M=N=K=4096, both row-major, NT form)
// 128x128 block tile, BK=32, 8x8 per-thread microtile, register prefetch.
// ---------------------------------------------------------------------------
__global__ void __launch_bounds__(256, 2)
gemm_nt(const float* __restrict__ A, const float* __restrict__ W,
        float* __restrict__ C)
{
    __shared__ float As[32][128];
    __shared__ float Ws[32][128];

    const int tid = threadIdx.x;
    const int bx = blockIdx.x;   // N dim
    const int by = blockIdx.y;   // M dim
    const int ty = tid >> 4;     // 0..15
    const int tx = tid & 15;     // 0..15

    float acc[8][8];
#pragma unroll
    for (int i = 0; i < 8; i++)
#pragma unroll
        for (int j = 0; j < 8; j++) acc[i][j] = 0.0f;

    // per-thread load coordinates (4 float4 per matrix per tile)
    // linear index li in 0..1023 -> row = li/8 (0..127), c4 = li%8 (k-chunk)
    // ---- load tile 0 ----
#pragma unroll
    for (int i = 0; i < 4; i++) {
        int li = tid + i * 256;
        int r  = li >> 3;
        int c4 = li & 7;
        float4 va = *(const float4*)&A[(size_t)(by * 128 + r) * 4096 + c4 * 4];
        float4 vw = *(const float4*)&W[(size_t)(bx * 128 + r) * 4096 + c4 * 4];
        As[c4*4+0][r] = va.x; As[c4*4+1][r] = va.y;
        As[c4*4+2][r] = va.z; As[c4*4+3][r] = va.w;
        Ws[c4*4+0][r] = vw.x; Ws[c4*4+1][r] = vw.y;
        Ws[c4*4+2][r] = vw.z; Ws[c4*4+3][r] = vw.w;
    }
    __syncthreads();

    const int NT = 4096 / 32;   // 128 k-tiles
    for (int kt = 0; kt < NT; kt++) {
        float4 ra[4], rw[4];
        if (kt + 1 < NT) {
            int k0 = (kt + 1) * 32;
#pragma unroll
            for (int i = 0; i < 4; i++) {
                int li = tid + i * 256;
                int r  = li >> 3;
                int c4 = li & 7;
                ra[i] = *(const float4*)&A[(size_t)(by*128 + r)*4096 + k0 + c4*4];
                rw[i] = *(const float4*)&W[(size_t)(bx*128 + r)*4096 + k0 + c4*4];
            }
        }

#pragma unroll 8
        for (int k = 0; k < 32; k++) {
            float a[8], b[8];
            *(float4*)&a[0] = *(float4*)&As[k][ty * 8];
            *(float4*)&a[4] = *(float4*)&As[k][ty * 8 + 4];
            *(float4*)&b[0] = *(float4*)&Ws[k][tx * 8];
            *(float4*)&b[4] = *(float4*)&Ws[k][tx * 8 + 4];
#pragma unroll
            for (int i = 0; i < 8; i++)
#pragma unroll
                for (int j = 0; j < 8; j++)
                    acc[i][j] = fmaf(a[i], b[j], acc[i][j]);
        }
        __syncthreads();

        if (kt + 1 < NT) {
#pragma unroll
            for (int i = 0; i < 4; i++) {
                int li = tid + i * 256;
                int r  = li >> 3;
                int c4 = li & 7;
                As[c4*4+0][r] = ra[i].x; As[c4*4+1][r] = ra[i].y;
                As[c4*4+2][r] = ra[i].z; As[c4*4+3][r] = ra[i].w;
                Ws[c4*4+0][r] = rw[i].x; Ws[c4*4+1][r] = rw[i].y;
                Ws[c4*4+2][r] = rw[i].z; Ws[c4*4+3][r] = rw[i].w;
            }
        }
        __syncthreads();
    }

    // epilogue
#pragma unroll
    for (int i = 0; i < 8; i++) {
        size_t cr = (size_t)(by * 128 + ty * 8 + i) * 4096 + bx * 128 + tx * 8;
        *(float4*)&C[cr]     = make_float4(acc[i][0], acc[i][1], acc[i][2], acc[i][3]);
        *(float4*)&C[cr + 4] = make_float4(acc[i][4], acc[i][5], acc[i][6], acc[i][7]);
    }
}

// ---------------------------------------------------------------------------
// RoPE cos/sin table (fp64 compute for accuracy; tiny, one-off cost)
// ---------------------------------------------------------------------------
__global__ void rope_table(float* ct, float* st)
{
    int idx = blockIdx.x * 256 + threadIdx.x;
    if (idx >= SEQ * (HD / 2)) return;
    int s = idx >> 6;
    int j = idx & 63;
    double inv = pow(10000.0, -(double)(2 * j) / 128.0);
    double a = (double)s * inv;
    ct[idx] = (float)cos(a);
    st[idx] = (float)sin(a);
}

// ---------------------------------------------------------------------------
// Interleaved RoPE applied in-place to q and k: pairs (2j, 2j+1)
// ---------------------------------------------------------------------------
__global__ void rope_apply(float* __restrict__ q, float* __restrict__ k,
                           const float* __restrict__ ct, const float* __restrict__ st)
{
    int idx = blockIdx.x * 256 + threadIdx.x;      // over B*S*H*64 = 8,388,608 pairs
    if (idx >= BSZ * SEQ * NH * (HD / 2)) return;
    int j = idx & 63;
    int h = (idx >> 6) & 31;
    int s = (idx >> 11) & 2047;
    int b = idx >> 22;
    size_t base = (((size_t)(b * SEQ + s) * NH + h) << 7) + 2 * j;
    float c  = ct[s * 64 + j];
    float sn = st[s * 64 + j];

    float2 xq = *(float2*)&q[base];
    float2 xk = *(float2*)&k[base];
    float2 oq, ok;
    oq.x = xq.x * c - xq.y * sn;
    oq.y = xq.x * sn + xq.y * c;
    ok.x = xk.x * c - xk.y * sn;
    ok.y = xk.x * sn + xk.y * c;
    *(float2*)&q[base] = oq;
    *(float2*)&k[base] = ok;
}

// ---------------------------------------------------------------------------
// Causal flash attention, fp32, online softmax.
// Block = 256 threads = 8 warps; block handles 32 q rows; warp handles 4 rows.
// K/V staged in shared as 32-key tiles.
// Q,K,V layout: [B, S, H, HD]; O layout: [B, S, H*HD] (same linearization).
// ---------------------------------------------------------------------------
__global__ void __launch_bounds__(256)
flash_attn(const float* __restrict__ Q, const float* __restrict__ Kg,
           const float* __restrict__ Vg, float* __restrict__ O)
{
    __shared__ float Ks[32][128];
    __shared__ float Vs[32][128];

    const int qt = blockIdx.x;           // q tile (32 rows)
    const int h  = blockIdx.y;
    const int b  = blockIdx.z;
    const int tid  = threadIdx.x;
    const int w    = tid >> 5;
    const int lane = tid & 31;
    const int q0 = qt * 32;
    const float scale = 0.08838834764831845f;   // 1/sqrt(128)

    float4 q4[4], o4[4];
    float m[4], l[4];
#pragma unroll
    for (int rr = 0; rr < 4; rr++) {
        int qg = q0 + w * 4 + rr;
        q4[rr] = *(const float4*)&Q[(((size_t)b * SEQ + qg) * NH + h) * HD + lane * 4];
        m[rr] = -1e30f;
        l[rr] = 0.0f;
        o4[rr] = make_float4(0.f, 0.f, 0.f, 0.f);
    }

    for (int kt = 0; kt <= qt; kt++) {
        const int k0 = kt * 32;
        // stage K,V tile: 32 rows x 32 float4
#pragma unroll
        for (int i = 0; i < 4; i++) {
            int li = tid + i * 256;          // 0..1023
            int kr = li >> 5;                // key row in tile
            int c  = li & 31;                // float4 chunk
            size_t gbase = (((size_t)b * SEQ + k0 + kr) * NH + h) * HD + c * 4;
            *(float4*)&Ks[kr][c * 4] = *(const float4*)&Kg[gbase];
            *(float4*)&Vs[kr][c * 4] = *(const float4*)&Vg[gbase];
        }
        __syncthreads();

        const bool diag = (kt == qt);
        for (int kk = 0; kk < 32; kk++) {
            float4 k4 = *(float4*)&Ks[kk][lane * 4];
            float4 v4 = *(float4*)&Vs[kk][lane * 4];
            int kg = k0 + kk;
#pragma unroll
            for (int rr = 0; rr < 4; rr++) {
                float p = q4[rr].x * k4.x + q4[rr].y * k4.y
                        + q4[rr].z * k4.z + q4[rr].w * k4.w;
                p += __shfl_xor_sync(0xffffffffu, p, 16);
                p += __shfl_xor_sync(0xffffffffu, p, 8);
                p += __shfl_xor_sync(0xffffffffu, p, 4);
                p += __shfl_xor_sync(0xffffffffu, p, 2);
                p += __shfl_xor_sync(0xffffffffu, p, 1);
                int qg = q0 + w * 4 + rr;
                if (!diag || kg <= qg) {
                    float s  = p * scale;
                    float mn = fmaxf(m[rr], s);
                    float f  = __expf(m[rr] - mn);
                    float e  = __expf(s - mn);
                    l[rr] = l[rr] * f + e;
                    o4[rr].x = o4[rr].x * f + e * v4.x;
                    o4[rr].y = o4[rr].y * f + e * v4.y;
                    o4[rr].z = o4[rr].z * f + e * v4.z;
                    o4[rr].w = o4[rr].w * f + e * v4.w;
                    m[rr] = mn;
                }
            }
        }
        __syncthreads();
    }

#pragma unroll
    for (int rr = 0; rr < 4; rr++) {
        int qg = q0 + w * 4 + rr;
        float inv = 1.0f / l[rr];
        float4 r = make_float4(o4[rr].x * inv, o4[rr].y * inv,
                               o4[rr].z * inv, o4[rr].w * inv);
        *(float4*)&O[(size_t)(b * SEQ + qg) * DIM + h * HD + lane * 4] = r;
    }
}

// ---------------------------------------------------------------------------
extern "C" void kernel_launch(void* const* d_in, const int* in_sizes, int n_in,
                              void* d_out, int out_size)
{
    const float* x = (const float*)d_in[0];
    // inputs: x, start_pos, wq, wk, wv, wo — start_pos is 0, ignored.
    // Defensive: if the scalar isn't materialized as an input, weights shift.
    int off = (n_in >= 6 && in_sizes[1] <= 4) ? 2 : 1;
    const float* wq = (const float*)d_in[off + 0];
    const float* wk = (const float*)d_in[off + 1];
    const float* wv = (const float*)d_in[off + 2];
    const float* wo = (const float*)d_in[off + 3];
    float* out = (float*)d_out;

    float *q, *k, *v, *attn, *ct, *st;
    cudaGetSymbolAddress((void**)&q,    g_q);
    cudaGetSymbolAddress((void**)&k,    g_k);
    cudaGetSymbolAddress((void**)&v,    g_v);
    cudaGetSymbolAddress((void**)&attn, g_attn);
    cudaGetSymbolAddress((void**)&ct,   g_cos);
    cudaGetSymbolAddress((void**)&st,   g_sin);

    dim3 gg(4096 / 128, 4096 / 128);   // (N tiles, M tiles)

    gemm_nt<<<gg, 256>>>(x, wq, q);
    gemm_nt<<<gg, 256>>>(x, wk, k);
    gemm_nt<<<gg, 256>>>(x, wv, v);

    rope_table<<<(SEQ * (HD / 2) + 255) / 256, 256>>>(ct, st);
    rope_apply<<<(BSZ * SEQ * NH * (HD / 2) + 255) / 256, 256>>>(q, k, ct, st);

    flash_attn<<<dim3(SEQ / 32, NH, BSZ), 256>>>(q, k, v, attn);

    gemm_nt<<<gg, 256>>>(attn, wo, out);
}

// round 3
// speedup vs baseline: 1.8776x; 1.8776x over previous
#include <cuda_runtime.h>
#include <cuda_bf16.h>
#include <cstdint>
#include <math.h>

#define DIM   4096
#define NH    32
#define HD    128
#define BSZ   2
#define SEQ   2048

// ---------------- scratch (__device__ globals; no allocs allowed) ----------
__device__ float g_q[BSZ*SEQ*DIM];
__device__ float g_k[BSZ*SEQ*DIM];
__device__ float g_v[BSZ*SEQ*DIM];
__device__ float g_attn[BSZ*SEQ*DIM];
__device__ float g_cos[SEQ*(HD/2)];
__device__ float g_sin[SEQ*(HD/2)];

// bf16 split buffers (hi/lo)
__device__ __nv_bfloat16 g_xhi[DIM*DIM],  g_xlo[DIM*DIM];
__device__ __nv_bfloat16 g_wqhi[DIM*DIM], g_wqlo[DIM*DIM];
__device__ __nv_bfloat16 g_wkhi[DIM*DIM], g_wklo[DIM*DIM];
__device__ __nv_bfloat16 g_wvhi[DIM*DIM], g_wvlo[DIM*DIM];
__device__ __nv_bfloat16 g_wohi[DIM*DIM], g_wolo[DIM*DIM];
__device__ __nv_bfloat16 g_ahi[DIM*DIM],  g_alo[DIM*DIM];

// ---------------- base-ISA helpers (work at compute_103) -------------------
__device__ __forceinline__ uint32_t smem_u32(const void* p) {
    uint32_t a;
    asm("{ .reg .u64 t; cvta.to.shared.u64 t, %1; cvt.u32.u64 %0, t; }" : "=r"(a) : "l"(p));
    return a;
}
__device__ __forceinline__ void cpa16(uint32_t saddr, const void* g) {
    asm volatile("cp.async.cg.shared.global [%0], [%1], 16;" :: "r"(saddr), "l"(g));
}
__device__ __forceinline__ void ldsm4(uint32_t* r, uint32_t addr) {
    asm volatile("ldmatrix.sync.aligned.m8n8.x4.shared.b16 {%0,%1,%2,%3}, [%4];"
        : "=r"(r[0]), "=r"(r[1]), "=r"(r[2]), "=r"(r[3]) : "r"(addr));
}
__device__ __forceinline__ void mma16816(float* c, const uint32_t* a,
                                         uint32_t b0, uint32_t b1) {
    asm volatile("mma.sync.aligned.m16n8k16.row.col.f32.bf16.bf16.f32 "
        "{%0,%1,%2,%3}, {%4,%5,%6,%7}, {%8,%9}, {%0,%1,%2,%3};"
        : "+f"(c[0]), "+f"(c[1]), "+f"(c[2]), "+f"(c[3])
        : "r"(a[0]), "r"(a[1]), "r"(a[2]), "r"(a[3]), "r"(b0), "r"(b1));
}
// SW64-style swizzle for 64-byte rows (conflict-free ldmatrix)
__device__ __forceinline__ uint32_t sw64(uint32_t off) {
    return off ^ ((off >> 3) & 0x30);
}

// ---------------------------------------------------------------------------
// fp32 -> (bf16 hi, bf16 lo) split, vectorized
// ---------------------------------------------------------------------------
__global__ void split_bf16(const float* __restrict__ in,
                           __nv_bfloat16* __restrict__ hi,
                           __nv_bfloat16* __restrict__ lo, int n4)
{
    int i = blockIdx.x * 256 + threadIdx.x;
    if (i >= n4) return;
    float4 v = ((const float4*)in)[i];
    __nv_bfloat162 h01 = __floats2bfloat162_rn(v.x, v.y);
    __nv_bfloat162 h23 = __floats2bfloat162_rn(v.z, v.w);
    float2 f01 = __bfloat1622float2(h01);
    float2 f23 = __bfloat1622float2(h23);
    __nv_bfloat162 l01 = __floats2bfloat162_rn(v.x - f01.x, v.y - f01.y);
    __nv_bfloat162 l23 = __floats2bfloat162_rn(v.z - f23.x, v.w - f23.y);
    ((__nv_bfloat162*)hi)[2*i]   = h01;
    ((__nv_bfloat162*)hi)[2*i+1] = h23;
    ((__nv_bfloat162*)lo)[2*i]   = l01;
    ((__nv_bfloat162*)lo)[2*i+1] = l23;
}

// ---------------------------------------------------------------------------
// Split-bf16 tensor-core GEMM (NT): C[m,n] = sum_k A[m,k]*W[n,k], 4096^3
// mma.sync m16n8k16 bf16. 128x128 block tile, BK=32, 8 warps (4Mx2N),
// warp tile 32x64, cp.async double buffering.
// ---------------------------------------------------------------------------
__global__ void __launch_bounds__(256)
gemm_mma(const __nv_bfloat16* __restrict__ Ahi, const __nv_bfloat16* __restrict__ Alo,
         const __nv_bfloat16* __restrict__ Bhi, const __nv_bfloat16* __restrict__ Blo,
         float* __restrict__ C)
{
    extern __shared__ char sm[];
    const uint32_t s0 = smem_u32(sm);

    const int tid  = threadIdx.x;
    const int wid  = tid >> 5;
    const int lane = tid & 31;
    const int bx = blockIdx.x;   // N tile
    const int by = blockIdx.y;   // M tile
    const int warp_m = wid >> 1; // 0..3
    const int warp_n = wid & 1;  // 0..1

    float acc[2][8][4];
#pragma unroll
    for (int t = 0; t < 2; t++)
#pragma unroll
        for (int n = 0; n < 8; n++)
#pragma unroll
            for (int j = 0; j < 4; j++) acc[t][n][j] = 0.0f;

    const __nv_bfloat16* gp[4] = {Ahi, Alo, Bhi, Blo};

    // stage layout: stage*32768 + mat*8192; mat rows 128 x 32 bf16 (64B rows)
    auto load_stage = [&](int kt, int stage) {
        uint32_t sbase = s0 + stage * 32768;
#pragma unroll
        for (int m = 0; m < 4; m++) {
            const int rowbase = (m < 2 ? by : bx) * 128;
            const __nv_bfloat16* G = gp[m];
#pragma unroll
            for (int i = 0; i < 2; i++) {
                int li = tid + i * 256;            // 0..511
                int r = li >> 2, c = li & 3;       // row, 16B chunk
                const void* g = G + (size_t)(rowbase + r) * 4096 + kt * 32 + c * 8;
                cpa16(sbase + m * 8192 + sw64((uint32_t)(r * 64 + c * 16)), g);
            }
        }
        asm volatile("cp.async.commit_group;" ::: "memory");
    };

    load_stage(0, 0);
    asm volatile("cp.async.wait_group 0;" ::: "memory");
    __syncthreads();

    const int lrow = (lane & 7) + ((lane >> 3) & 1) * 8;
    const int khalf = (lane >> 4) * 16;            // byte offset of k-half

    const int NT = 4096 / 32;
    for (int kt = 0; kt < NT; kt++) {
        const int stage = kt & 1;
        if (kt + 1 < NT) load_stage(kt + 1, stage ^ 1);

        const uint32_t sAhi = s0 + stage * 32768;
        const uint32_t sAlo = sAhi + 8192;
        const uint32_t sBhi = sAhi + 16384;
        const uint32_t sBlo = sAhi + 24576;

#pragma unroll
        for (int s = 0; s < 2; s++) {              // two k16 steps in BK=32
            uint32_t ahi[2][4], alo[2][4];
#pragma unroll
            for (int t = 0; t < 2; t++) {
                uint32_t off = sw64((uint32_t)((warp_m * 32 + t * 16 + lrow) * 64
                                               + khalf + s * 32));
                ldsm4(ahi[t], sAhi + off);
                ldsm4(alo[t], sAlo + off);
            }
            uint32_t bhi[4][4], blo[4][4];
#pragma unroll
            for (int u = 0; u < 4; u++) {
                uint32_t off = sw64((uint32_t)((warp_n * 64 + u * 16 + lrow) * 64
                                               + khalf + s * 32));
                ldsm4(bhi[u], sBhi + off);
                ldsm4(blo[u], sBlo + off);
            }
#pragma unroll
            for (int t = 0; t < 2; t++)
#pragma unroll
                for (int u = 0; u < 4; u++)
#pragma unroll
                    for (int j = 0; j < 2; j++) {
                        float* c = acc[t][u * 2 + j];
                        mma16816(c, ahi[t], bhi[u][j], bhi[u][j + 2]);
                        mma16816(c, ahi[t], blo[u][j], blo[u][j + 2]);
                        mma16816(c, alo[t], bhi[u][j], bhi[u][j + 2]);
                    }
        }

        if (kt + 1 < NT) asm volatile("cp.async.wait_group 0;" ::: "memory");
        __syncthreads();
    }

    // epilogue: c fragment (g=lane/4 row, 2*(lane%4) col; c2,c3 at row+8)
    const int g  = lane >> 2;
    const int qc = lane & 3;
#pragma unroll
    for (int t = 0; t < 2; t++) {
        const int row = by * 128 + warp_m * 32 + t * 16 + g;
#pragma unroll
        for (int n = 0; n < 8; n++) {
            const int col = bx * 128 + warp_n * 64 + n * 8 + qc * 2;
            *(float2*)&C[(size_t)row * 4096 + col] =
                make_float2(acc[t][n][0], acc[t][n][1]);
            *(float2*)&C[(size_t)(row + 8) * 4096 + col] =
                make_float2(acc[t][n][2], acc[t][n][3]);
        }
    }
}

// ---------------------------------------------------------------------------
// RoPE table (fp64 for accuracy)
// ---------------------------------------------------------------------------
__global__ void rope_table(float* ct, float* st)
{
    int idx = blockIdx.x * 256 + threadIdx.x;
    if (idx >= SEQ * (HD / 2)) return;
    int s = idx >> 6;
    int j = idx & 63;
    double inv = pow(10000.0, -(double)(2 * j) / 128.0);
    double a = (double)s * inv;
    ct[idx] = (float)cos(a);
    st[idx] = (float)sin(a);
}

__global__ void rope_apply(float* __restrict__ q, float* __restrict__ k,
                           const float* __restrict__ ct, const float* __restrict__ st)
{
    int idx = blockIdx.x * 256 + threadIdx.x;
    if (idx >= BSZ * SEQ * NH * (HD / 2)) return;
    int j = idx & 63;
    int h = (idx >> 6) & 31;
    int s = (idx >> 11) & 2047;
    int b = idx >> 22;
    size_t base = (((size_t)(b * SEQ + s) * NH + h) << 7) + 2 * j;
    float c  = ct[s * 64 + j];
    float sn = st[s * 64 + j];
    float2 xq = *(float2*)&q[base];
    float2 xk = *(float2*)&k[base];
    float2 oq, ok;
    oq.x = xq.x * c - xq.y * sn;
    oq.y = xq.x * sn + xq.y * c;
    ok.x = xk.x * c - xk.y * sn;
    ok.y = xk.x * sn + xk.y * c;
    *(float2*)&q[base] = oq;
    *(float2*)&k[base] = ok;
}

// ---------------------------------------------------------------------------
// Causal flash attention, fp32, online softmax
// ---------------------------------------------------------------------------
__global__ void __launch_bounds__(256)
flash_attn(const float* __restrict__ Q, const float* __restrict__ Kg,
           const float* __restrict__ Vg, float* __restrict__ O)
{
    __shared__ float Ks[32][128];
    __shared__ float Vs[32][128];

    const int qt = blockIdx.x;
    const int h  = blockIdx.y;
    const int b  = blockIdx.z;
    const int tid  = threadIdx.x;
    const int w    = tid >> 5;
    const int lane = tid & 31;
    const int q0 = qt * 32;
    const float scale = 0.08838834764831845f;

    float4 q4[4], o4[4];
    float m[4], l[4];
#pragma unroll
    for (int rr = 0; rr < 4; rr++) {
        int qg = q0 + w * 4 + rr;
        q4[rr] = *(const float4*)&Q[(((size_t)b * SEQ + qg) * NH + h) * HD + lane * 4];
        m[rr] = -1e30f;
        l[rr] = 0.0f;
        o4[rr] = make_float4(0.f, 0.f, 0.f, 0.f);
    }

    for (int kt = 0; kt <= qt; kt++) {
        const int k0 = kt * 32;
#pragma unroll
        for (int i = 0; i < 4; i++) {
            int li = tid + i * 256;
            int kr = li >> 5;
            int c  = li & 31;
            size_t gbase = (((size_t)b * SEQ + k0 + kr) * NH + h) * HD + c * 4;
            *(float4*)&Ks[kr][c * 4] = *(const float4*)&Kg[gbase];
            *(float4*)&Vs[kr][c * 4] = *(const float4*)&Vg[gbase];
        }
        __syncthreads();

        const bool diag = (kt == qt);
        for (int kk = 0; kk < 32; kk++) {
            float4 k4 = *(float4*)&Ks[kk][lane * 4];
            float4 v4 = *(float4*)&Vs[kk][lane * 4];
            int kg = k0 + kk;
#pragma unroll
            for (int rr = 0; rr < 4; rr++) {
                float p = q4[rr].x * k4.x + q4[rr].y * k4.y
                        + q4[rr].z * k4.z + q4[rr].w * k4.w;
                p += __shfl_xor_sync(0xffffffffu, p, 16);
                p += __shfl_xor_sync(0xffffffffu, p, 8);
                p += __shfl_xor_sync(0xffffffffu, p, 4);
                p += __shfl_xor_sync(0xffffffffu, p, 2);
                p += __shfl_xor_sync(0xffffffffu, p, 1);
                int qg = q0 + w * 4 + rr;
                if (!diag || kg <= qg) {
                    float s  = p * scale;
                    float mn = fmaxf(m[rr], s);
                    float f  = __expf(m[rr] - mn);
                    float e  = __expf(s - mn);
                    l[rr] = l[rr] * f + e;
                    o4[rr].x = o4[rr].x * f + e * v4.x;
                    o4[rr].y = o4[rr].y * f + e * v4.y;
                    o4[rr].z = o4[rr].z * f + e * v4.z;
                    o4[rr].w = o4[rr].w * f + e * v4.w;
                    m[rr] = mn;
                }
            }
        }
        __syncthreads();
    }

#pragma unroll
    for (int rr = 0; rr < 4; rr++) {
        int qg = q0 + w * 4 + rr;
        float inv = 1.0f / l[rr];
        float4 r = make_float4(o4[rr].x * inv, o4[rr].y * inv,
                               o4[rr].z * inv, o4[rr].w * inv);
        *(float4*)&O[(size_t)(b * SEQ + qg) * DIM + h * HD + lane * 4] = r;
    }
}

// ---------------------------------------------------------------------------
extern "C" void kernel_launch(void* const* d_in, const int* in_sizes, int n_in,
                              void* d_out, int out_size)
{
    const float* x = (const float*)d_in[0];
    int off = (n_in >= 6 && in_sizes[1] <= 4) ? 2 : 1;
    const float* wq = (const float*)d_in[off + 0];
    const float* wk = (const float*)d_in[off + 1];
    const float* wv = (const float*)d_in[off + 2];
    const float* wo = (const float*)d_in[off + 3];
    float* out = (float*)d_out;

    float *q, *k, *v, *attn, *ct, *st;
    cudaGetSymbolAddress((void**)&q,    g_q);
    cudaGetSymbolAddress((void**)&k,    g_k);
    cudaGetSymbolAddress((void**)&v,    g_v);
    cudaGetSymbolAddress((void**)&attn, g_attn);
    cudaGetSymbolAddress((void**)&ct,   g_cos);
    cudaGetSymbolAddress((void**)&st,   g_sin);

    __nv_bfloat16 *xhi, *xlo, *wqhi, *wqlo, *wkhi, *wklo, *wvhi, *wvlo, *wohi, *wolo, *ahi, *alo;
    cudaGetSymbolAddress((void**)&xhi,  g_xhi);   cudaGetSymbolAddress((void**)&xlo,  g_xlo);
    cudaGetSymbolAddress((void**)&wqhi, g_wqhi);  cudaGetSymbolAddress((void**)&wqlo, g_wqlo);
    cudaGetSymbolAddress((void**)&wkhi, g_wkhi);  cudaGetSymbolAddress((void**)&wklo, g_wklo);
    cudaGetSymbolAddress((void**)&wvhi, g_wvhi);  cudaGetSymbolAddress((void**)&wvlo, g_wvlo);
    cudaGetSymbolAddress((void**)&wohi, g_wohi);  cudaGetSymbolAddress((void**)&wolo, g_wolo);
    cudaGetSymbolAddress((void**)&ahi,  g_ahi);   cudaGetSymbolAddress((void**)&alo,  g_alo);

    cudaFuncSetAttribute(gemm_mma, cudaFuncAttributeMaxDynamicSharedMemorySize, 65536);

    const int n4 = DIM * DIM / 4;
    const int cgrid = (n4 + 255) / 256;

    split_bf16<<<cgrid, 256>>>(x,  xhi, xlo, n4);
    split_bf16<<<cgrid, 256>>>(wq, wqhi, wqlo, n4);
    split_bf16<<<cgrid, 256>>>(wk, wkhi, wklo, n4);
    split_bf16<<<cgrid, 256>>>(wv, wvhi, wvlo, n4);
    split_bf16<<<cgrid, 256>>>(wo, wohi, wolo, n4);

    dim3 gg(DIM / 128, DIM / 128);
    gemm_mma<<<gg, 256, 65536>>>(xhi, xlo, wqhi, wqlo, q);
    gemm_mma<<<gg, 256, 65536>>>(xhi, xlo, wkhi, wklo, k);
    gemm_mma<<<gg, 256, 65536>>>(xhi, xlo, wvhi, wvlo, v);

    rope_table<<<(SEQ * (HD / 2) + 255) / 256, 256>>>(ct, st);
    rope_apply<<<(BSZ * SEQ * NH * (HD / 2) + 255) / 256, 256>>>(q, k, ct, st);

    flash_attn<<<dim3(SEQ / 32, NH, BSZ), 256>>>(q, k, v, attn);

    split_bf16<<<cgrid, 256>>>(attn, ahi, alo, n4);
    gemm_mma<<<gg, 256, 65536>>>(ahi, alo, wohi, wolo, out);
}

// round 4
// speedup vs baseline: 4.3253x; 2.3037x over previous
#include <cuda_runtime.h>
#include <cuda_bf16.h>
#include <cstdint>
#include <math.h>

#define DIM   4096
#define NH    32
#define HD    128
#define BSZ   2
#define SEQ   2048

// ---------------- scratch (__device__ globals; no allocs allowed) ----------
__device__ float g_q[BSZ*SEQ*DIM];
__device__ float g_k[BSZ*SEQ*DIM];
__device__ float g_v[BSZ*SEQ*DIM];
__device__ float g_attn[BSZ*SEQ*DIM];
__device__ float g_cos[SEQ*(HD/2)];
__device__ float g_sin[SEQ*(HD/2)];

// bf16 split buffers (hi/lo)
__device__ __nv_bfloat16 g_xhi[DIM*DIM],  g_xlo[DIM*DIM];
__device__ __nv_bfloat16 g_wqhi[DIM*DIM], g_wqlo[DIM*DIM];
__device__ __nv_bfloat16 g_wkhi[DIM*DIM], g_wklo[DIM*DIM];
__device__ __nv_bfloat16 g_wvhi[DIM*DIM], g_wvlo[DIM*DIM];
__device__ __nv_bfloat16 g_wohi[DIM*DIM], g_wolo[DIM*DIM];
__device__ __nv_bfloat16 g_ahi[DIM*DIM],  g_alo[DIM*DIM];

// ---------------- base-ISA helpers (compute_103-safe) ----------------------
__device__ __forceinline__ uint32_t smem_u32(const void* p) {
    uint32_t a;
    asm("{ .reg .u64 t; cvta.to.shared.u64 t, %1; cvt.u32.u64 %0, t; }" : "=r"(a) : "l"(p));
    return a;
}
__device__ __forceinline__ void cpa16(uint32_t saddr, const void* g) {
    asm volatile("cp.async.cg.shared.global [%0], [%1], 16;" :: "r"(saddr), "l"(g));
}
__device__ __forceinline__ void ldsm4(uint32_t* r, uint32_t addr) {
    asm volatile("ldmatrix.sync.aligned.m8n8.x4.shared.b16 {%0,%1,%2,%3}, [%4];"
        : "=r"(r[0]), "=r"(r[1]), "=r"(r[2]), "=r"(r[3]) : "r"(addr));
}
__device__ __forceinline__ void mma16816(float* c, const uint32_t* a,
                                         uint32_t b0, uint32_t b1) {
    asm volatile("mma.sync.aligned.m16n8k16.row.col.f32.bf16.bf16.f32 "
        "{%0,%1,%2,%3}, {%4,%5,%6,%7}, {%8,%9}, {%0,%1,%2,%3};"
        : "+f"(c[0]), "+f"(c[1]), "+f"(c[2]), "+f"(c[3])
        : "r"(a[0]), "r"(a[1]), "r"(a[2]), "r"(a[3]), "r"(b0), "r"(b1));
}
__device__ __forceinline__ void mma_tf32(float* c, const uint32_t* a,
                                         uint32_t b0, uint32_t b1) {
    asm volatile("mma.sync.aligned.m16n8k8.row.col.f32.tf32.tf32.f32 "
        "{%0,%1,%2,%3}, {%4,%5,%6,%7}, {%8,%9}, {%0,%1,%2,%3};"
        : "+f"(c[0]), "+f"(c[1]), "+f"(c[2]), "+f"(c[3])
        : "r"(a[0]), "r"(a[1]), "r"(a[2]), "r"(a[3]), "r"(b0), "r"(b1));
}
__device__ __forceinline__ uint32_t to_tf32(float x) {
    uint32_t r;
    asm("cvt.rna.tf32.f32 %0, %1;" : "=r"(r) : "f"(x));
    return r;
}
__device__ __forceinline__ uint32_t sw64(uint32_t off) {
    return off ^ ((off >> 3) & 0x30);
}

// ---------------------------------------------------------------------------
// fp32 -> (bf16 hi, bf16 lo) split, vectorized
// ---------------------------------------------------------------------------
__global__ void split_bf16(const float* __restrict__ in,
                           __nv_bfloat16* __restrict__ hi,
                           __nv_bfloat16* __restrict__ lo, int n4)
{
    int i = blockIdx.x * 256 + threadIdx.x;
    if (i >= n4) return;
    float4 v = ((const float4*)in)[i];
    __nv_bfloat162 h01 = __floats2bfloat162_rn(v.x, v.y);
    __nv_bfloat162 h23 = __floats2bfloat162_rn(v.z, v.w);
    float2 f01 = __bfloat1622float2(h01);
    float2 f23 = __bfloat1622float2(h23);
    __nv_bfloat162 l01 = __floats2bfloat162_rn(v.x - f01.x, v.y - f01.y);
    __nv_bfloat162 l23 = __floats2bfloat162_rn(v.z - f23.x, v.w - f23.y);
    ((__nv_bfloat162*)hi)[2*i]   = h01;
    ((__nv_bfloat162*)hi)[2*i+1] = h23;
    ((__nv_bfloat162*)lo)[2*i]   = l01;
    ((__nv_bfloat162*)lo)[2*i+1] = l23;
}

// ---------------------------------------------------------------------------
// Split-bf16 tensor-core GEMM (NT), 3-stage cp.async pipeline.
// 128x128 block tile, BK=32, 8 warps (4Mx2N), warp tile 32x64.
// ---------------------------------------------------------------------------
__global__ void __launch_bounds__(256)
gemm_mma(const __nv_bfloat16* __restrict__ Ahi, const __nv_bfloat16* __restrict__ Alo,
         const __nv_bfloat16* __restrict__ Bhi, const __nv_bfloat16* __restrict__ Blo,
         float* __restrict__ C)
{
    extern __shared__ char sm[];
    const uint32_t s0 = smem_u32(sm);

    const int tid  = threadIdx.x;
    const int wid  = tid >> 5;
    const int lane = tid & 31;
    const int bx = blockIdx.x;
    const int by = blockIdx.y;
    const int warp_m = wid >> 1;
    const int warp_n = wid & 1;

    float acc[2][8][4];
#pragma unroll
    for (int t = 0; t < 2; t++)
#pragma unroll
        for (int n = 0; n < 8; n++)
#pragma unroll
            for (int j = 0; j < 4; j++) acc[t][n][j] = 0.0f;

    const __nv_bfloat16* gp[4] = {Ahi, Alo, Bhi, Blo};

    auto load_stage = [&](int kt, int stage) {
        uint32_t sbase = s0 + stage * 32768;
#pragma unroll
        for (int m = 0; m < 4; m++) {
            const int rowbase = (m < 2 ? by : bx) * 128;
            const __nv_bfloat16* G = gp[m];
#pragma unroll
            for (int i = 0; i < 2; i++) {
                int li = tid + i * 256;
                int r = li >> 2, c = li & 3;
                const void* g = G + (size_t)(rowbase + r) * 4096 + kt * 32 + c * 8;
                cpa16(sbase + m * 8192 + sw64((uint32_t)(r * 64 + c * 16)), g);
            }
        }
        asm volatile("cp.async.commit_group;" ::: "memory");
    };

    const int NT = 4096 / 32;   // 128

    load_stage(0, 0);
    load_stage(1, 1);

    const int lrow = (lane & 7) + ((lane >> 3) & 1) * 8;
    const int khalf = (lane >> 4) * 16;

    for (int kt = 0; kt < NT; kt++) {
        if (kt < NT - 1) asm volatile("cp.async.wait_group 1;" ::: "memory");
        else             asm volatile("cp.async.wait_group 0;" ::: "memory");
        __syncthreads();

        if (kt + 2 < NT) load_stage(kt + 2, (kt + 2) % 3);

        const int stage = kt % 3;
        const uint32_t sAhi = s0 + stage * 32768;
        const uint32_t sAlo = sAhi + 8192;
        const uint32_t sBhi = sAhi + 16384;
        const uint32_t sBlo = sAhi + 24576;

#pragma unroll
        for (int s = 0; s < 2; s++) {
            uint32_t ahi[2][4], alo[2][4];
#pragma unroll
            for (int t = 0; t < 2; t++) {
                uint32_t off = sw64((uint32_t)((warp_m * 32 + t * 16 + lrow) * 64
                                               + khalf + s * 32));
                ldsm4(ahi[t], sAhi + off);
                ldsm4(alo[t], sAlo + off);
            }
            uint32_t bhi[4][4], blo[4][4];
#pragma unroll
            for (int u = 0; u < 4; u++) {
                uint32_t off = sw64((uint32_t)((warp_n * 64 + u * 16 + lrow) * 64
                                               + khalf + s * 32));
                ldsm4(bhi[u], sBhi + off);
                ldsm4(blo[u], sBlo + off);
            }
#pragma unroll
            for (int t = 0; t < 2; t++)
#pragma unroll
                for (int u = 0; u < 4; u++)
#pragma unroll
                    for (int j = 0; j < 2; j++) {
                        float* c = acc[t][u * 2 + j];
                        mma16816(c, ahi[t], bhi[u][j], bhi[u][j + 2]);
                        mma16816(c, ahi[t], blo[u][j], blo[u][j + 2]);
                        mma16816(c, alo[t], bhi[u][j], bhi[u][j + 2]);
                    }
        }
    }

    const int g  = lane >> 2;
    const int qc = lane & 3;
#pragma unroll
    for (int t = 0; t < 2; t++) {
        const int row = by * 128 + warp_m * 32 + t * 16 + g;
#pragma unroll
        for (int n = 0; n < 8; n++) {
            const int col = bx * 128 + warp_n * 64 + n * 8 + qc * 2;
            *(float2*)&C[(size_t)row * 4096 + col] =
                make_float2(acc[t][n][0], acc[t][n][1]);
            *(float2*)&C[(size_t)(row + 8) * 4096 + col] =
                make_float2(acc[t][n][2], acc[t][n][3]);
        }
    }
}

// ---------------------------------------------------------------------------
// RoPE
// ---------------------------------------------------------------------------
__global__ void rope_table(float* ct, float* st)
{
    int idx = blockIdx.x * 256 + threadIdx.x;
    if (idx >= SEQ * (HD / 2)) return;
    int s = idx >> 6;
    int j = idx & 63;
    double inv = pow(10000.0, -(double)(2 * j) / 128.0);
    double a = (double)s * inv;
    ct[idx] = (float)cos(a);
    st[idx] = (float)sin(a);
}

__global__ void rope_apply(float* __restrict__ q, float* __restrict__ k,
                           const float* __restrict__ ct, const float* __restrict__ st)
{
    int idx = blockIdx.x * 256 + threadIdx.x;
    if (idx >= BSZ * SEQ * NH * (HD / 2)) return;
    int j = idx & 63;
    int h = (idx >> 6) & 31;
    int s = (idx >> 11) & 2047;
    int b = idx >> 22;
    size_t base = (((size_t)(b * SEQ + s) * NH + h) << 7) + 2 * j;
    float c  = ct[s * 64 + j];
    float sn = st[s * 64 + j];
    float2 xq = *(float2*)&q[base];
    float2 xk = *(float2*)&k[base];
    float2 oq, ok;
    oq.x = xq.x * c - xq.y * sn;
    oq.y = xq.x * sn + xq.y * c;
    ok.x = xk.x * c - xk.y * sn;
    ok.y = xk.x * sn + xk.y * c;
    *(float2*)&q[base] = oq;
    *(float2*)&k[base] = ok;
}

// ---------------------------------------------------------------------------
// Tensor-core causal flash attention (tf32 mma.m16n8k8).
// Block = 128 threads (4 warps). Q tile 64 rows (16/warp), K tile 64 keys.
// Q/K/V layout [B, S, NH, HD]; O layout [B, S, DIM].
// ---------------------------------------------------------------------------
#define KS_STRIDE 132
#define PS_STRIDE 68
#define ATTN_SMEM ((2*64*KS_STRIDE + 4*16*PS_STRIDE) * 4)

__global__ void __launch_bounds__(128)
attn_tc(const float* __restrict__ Q, const float* __restrict__ Kg,
        const float* __restrict__ Vg, float* __restrict__ O)
{
    extern __shared__ float smf[];
    float* Ks = smf;                        // [64][132] (tf32 bit patterns)
    float* Vs = smf + 64 * KS_STRIDE;       // [64][132]
    float* Ps = smf + 2 * 64 * KS_STRIDE;   // per warp [16][68]

    const int tid  = threadIdx.x;
    const int w    = tid >> 5;
    const int lane = tid & 31;
    const int qt = blockIdx.x;
    const int h  = blockIdx.y;
    const int b  = blockIdx.z;
    const int g  = lane >> 2;
    const int qc = lane & 3;
    float* Pw = Ps + w * 16 * PS_STRIDE;

    const float scale = 0.08838834764831845f;   // 1/sqrt(128)
    const int q0 = qt * 64 + w * 16;

    // Q a-fragments (scaled, tf32)
    uint32_t qa[16][4];
    {
        const float* q_r0 = Q + ((size_t)b * SEQ + q0 + g)     * 4096 + h * 128;
        const float* q_r1 = Q + ((size_t)b * SEQ + q0 + g + 8) * 4096 + h * 128;
#pragma unroll
        for (int kc = 0; kc < 16; kc++) {
            qa[kc][0] = to_tf32(q_r0[kc * 8 + qc]     * scale);
            qa[kc][1] = to_tf32(q_r1[kc * 8 + qc]     * scale);
            qa[kc][2] = to_tf32(q_r0[kc * 8 + qc + 4] * scale);
            qa[kc][3] = to_tf32(q_r1[kc * 8 + qc + 4] * scale);
        }
    }

    float o[16][4];
#pragma unroll
    for (int n = 0; n < 16; n++)
#pragma unroll
        for (int j = 0; j < 4; j++) o[n][j] = 0.0f;
    float m0 = -1e30f, m1 = -1e30f, l0 = 0.0f, l1 = 0.0f;

    for (int kt = 0; kt <= qt; kt++) {
        if (kt) __syncthreads();
        // stage K,V tiles (convert to tf32 bits)
#pragma unroll
        for (int i = 0; i < 16; i++) {
            int li = tid + i * 128;
            int row = li >> 5, c4 = li & 31;
            size_t gsrc = ((size_t)b * SEQ + kt * 64 + row) * 4096 + h * 128 + c4 * 4;
            float4 kv = *(const float4*)&Kg[gsrc];
            float4 vv = *(const float4*)&Vg[gsrc];
            uint4 kb = make_uint4(to_tf32(kv.x), to_tf32(kv.y), to_tf32(kv.z), to_tf32(kv.w));
            uint4 vb = make_uint4(to_tf32(vv.x), to_tf32(vv.y), to_tf32(vv.z), to_tf32(vv.w));
            *(uint4*)&Ks[row * KS_STRIDE + c4 * 4] = kb;
            *(uint4*)&Vs[row * KS_STRIDE + c4 * 4] = vb;
        }
        __syncthreads();

        // scores: S = Q K^T (16x64 per warp)
        float sreg[8][4];
#pragma unroll
        for (int j = 0; j < 8; j++) {
            sreg[j][0] = sreg[j][1] = sreg[j][2] = sreg[j][3] = 0.0f;
            const uint32_t* krow = (const uint32_t*)&Ks[(j * 8 + g) * KS_STRIDE];
#pragma unroll
            for (int kc = 0; kc < 16; kc++)
                mma_tf32(sreg[j], qa[kc], krow[kc * 8 + qc], krow[kc * 8 + qc + 4]);
        }

        // causal mask on the diagonal tile
        if (kt == qt) {
            const int kb = kt * 64;
#pragma unroll
            for (int j = 0; j < 8; j++) {
                int key0 = kb + j * 8 + 2 * qc;
                if (key0     > q0 + g)     sreg[j][0] = -1e30f;
                if (key0 + 1 > q0 + g)     sreg[j][1] = -1e30f;
                if (key0     > q0 + g + 8) sreg[j][2] = -1e30f;
                if (key0 + 1 > q0 + g + 8) sreg[j][3] = -1e30f;
            }
        }

        // online softmax
        float mx0 = -1e30f, mx1 = -1e30f;
#pragma unroll
        for (int j = 0; j < 8; j++) {
            mx0 = fmaxf(mx0, fmaxf(sreg[j][0], sreg[j][1]));
            mx1 = fmaxf(mx1, fmaxf(sreg[j][2], sreg[j][3]));
        }
        mx0 = fmaxf(mx0, __shfl_xor_sync(0xffffffffu, mx0, 1));
        mx0 = fmaxf(mx0, __shfl_xor_sync(0xffffffffu, mx0, 2));
        mx1 = fmaxf(mx1, __shfl_xor_sync(0xffffffffu, mx1, 1));
        mx1 = fmaxf(mx1, __shfl_xor_sync(0xffffffffu, mx1, 2));
        float mn0 = fmaxf(m0, mx0), mn1 = fmaxf(m1, mx1);
        float f0 = __expf(m0 - mn0), f1 = __expf(m1 - mn1);
        m0 = mn0; m1 = mn1;

        float sum0 = 0.0f, sum1 = 0.0f;
        uint32_t* PwU = (uint32_t*)Pw;
#pragma unroll
        for (int j = 0; j < 8; j++) {
            float p0 = __expf(sreg[j][0] - mn0);
            float p1 = __expf(sreg[j][1] - mn0);
            float p2 = __expf(sreg[j][2] - mn1);
            float p3 = __expf(sreg[j][3] - mn1);
            sum0 += p0 + p1;
            sum1 += p2 + p3;
            PwU[g * PS_STRIDE       + j * 8 + 2 * qc]     = to_tf32(p0);
            PwU[g * PS_STRIDE       + j * 8 + 2 * qc + 1] = to_tf32(p1);
            PwU[(g + 8) * PS_STRIDE + j * 8 + 2 * qc]     = to_tf32(p2);
            PwU[(g + 8) * PS_STRIDE + j * 8 + 2 * qc + 1] = to_tf32(p3);
        }
        sum0 += __shfl_xor_sync(0xffffffffu, sum0, 1);
        sum0 += __shfl_xor_sync(0xffffffffu, sum0, 2);
        sum1 += __shfl_xor_sync(0xffffffffu, sum1, 1);
        sum1 += __shfl_xor_sync(0xffffffffu, sum1, 2);
        l0 = l0 * f0 + sum0;
        l1 = l1 * f1 + sum1;

#pragma unroll
        for (int n = 0; n < 16; n++) {
            o[n][0] *= f0; o[n][1] *= f0;
            o[n][2] *= f1; o[n][3] *= f1;
        }
        __syncwarp();

        // P a-fragments
        uint32_t pa[8][4];
#pragma unroll
        for (int kc = 0; kc < 8; kc++) {
            pa[kc][0] = PwU[g * PS_STRIDE       + kc * 8 + qc];
            pa[kc][1] = PwU[(g + 8) * PS_STRIDE + kc * 8 + qc];
            pa[kc][2] = PwU[g * PS_STRIDE       + kc * 8 + qc + 4];
            pa[kc][3] = PwU[(g + 8) * PS_STRIDE + kc * 8 + qc + 4];
        }

        // O += P V
#pragma unroll
        for (int n = 0; n < 16; n++) {
#pragma unroll
            for (int kc = 0; kc < 8; kc++) {
                uint32_t b0 = ((const uint32_t*)Vs)[(kc * 8 + qc)     * KS_STRIDE + n * 8 + g];
                uint32_t b1 = ((const uint32_t*)Vs)[(kc * 8 + qc + 4) * KS_STRIDE + n * 8 + g];
                mma_tf32(o[n], pa[kc], b0, b1);
            }
        }
    }

    // epilogue
    const float inv0 = 1.0f / l0;
    const float inv1 = 1.0f / l1;
    float* o_r0 = O + ((size_t)b * SEQ + q0 + g)     * 4096 + h * 128;
    float* o_r1 = O + ((size_t)b * SEQ + q0 + g + 8) * 4096 + h * 128;
#pragma unroll
    for (int n = 0; n < 16; n++) {
        *(float2*)&o_r0[n * 8 + 2 * qc] = make_float2(o[n][0] * inv0, o[n][1] * inv0);
        *(float2*)&o_r1[n * 8 + 2 * qc] = make_float2(o[n][2] * inv1, o[n][3] * inv1);
    }
}

// ---------------------------------------------------------------------------
extern "C" void kernel_launch(void* const* d_in, const int* in_sizes, int n_in,
                              void* d_out, int out_size)
{
    const float* x = (const float*)d_in[0];
    int off = (n_in >= 6 && in_sizes[1] <= 4) ? 2 : 1;
    const float* wq = (const float*)d_in[off + 0];
    const float* wk = (const float*)d_in[off + 1];
    const float* wv = (const float*)d_in[off + 2];
    const float* wo = (const float*)d_in[off + 3];
    float* out = (float*)d_out;

    float *q, *k, *v, *attn, *ct, *st;
    cudaGetSymbolAddress((void**)&q,    g_q);
    cudaGetSymbolAddress((void**)&k,    g_k);
    cudaGetSymbolAddress((void**)&v,    g_v);
    cudaGetSymbolAddress((void**)&attn, g_attn);
    cudaGetSymbolAddress((void**)&ct,   g_cos);
    cudaGetSymbolAddress((void**)&st,   g_sin);

    __nv_bfloat16 *xhi, *xlo, *wqhi, *wqlo, *wkhi, *wklo, *wvhi, *wvlo, *wohi, *wolo, *ahi, *alo;
    cudaGetSymbolAddress((void**)&xhi,  g_xhi);   cudaGetSymbolAddress((void**)&xlo,  g_xlo);
    cudaGetSymbolAddress((void**)&wqhi, g_wqhi);  cudaGetSymbolAddress((void**)&wqlo, g_wqlo);
    cudaGetSymbolAddress((void**)&wkhi, g_wkhi);  cudaGetSymbolAddress((void**)&wklo, g_wklo);
    cudaGetSymbolAddress((void**)&wvhi, g_wvhi);  cudaGetSymbolAddress((void**)&wvlo, g_wvlo);
    cudaGetSymbolAddress((void**)&wohi, g_wohi);  cudaGetSymbolAddress((void**)&wolo, g_wolo);
    cudaGetSymbolAddress((void**)&ahi,  g_ahi);   cudaGetSymbolAddress((void**)&alo,  g_alo);

    cudaFuncSetAttribute(gemm_mma, cudaFuncAttributeMaxDynamicSharedMemorySize, 98304);
    cudaFuncSetAttribute(attn_tc,  cudaFuncAttributeMaxDynamicSharedMemorySize, ATTN_SMEM);

    const int n4 = DIM * DIM / 4;
    const int cgrid = (n4 + 255) / 256;

    split_bf16<<<cgrid, 256>>>(x,  xhi, xlo, n4);
    split_bf16<<<cgrid, 256>>>(wq, wqhi, wqlo, n4);
    split_bf16<<<cgrid, 256>>>(wk, wkhi, wklo, n4);
    split_bf16<<<cgrid, 256>>>(wv, wvhi, wvlo, n4);
    split_bf16<<<cgrid, 256>>>(wo, wohi, wolo, n4);

    dim3 gg(DIM / 128, DIM / 128);
    gemm_mma<<<gg, 256, 98304>>>(xhi, xlo, wqhi, wqlo, q);
    gemm_mma<<<gg, 256, 98304>>>(xhi, xlo, wkhi, wklo, k);
    gemm_mma<<<gg, 256, 98304>>>(xhi, xlo, wvhi, wvlo, v);

    rope_table<<<(SEQ * (HD / 2) + 255) / 256, 256>>>(ct, st);
    rope_apply<<<(BSZ * SEQ * NH * (HD / 2) + 255) / 256, 256>>>(q, k, ct, st);

    attn_tc<<<dim3(SEQ / 64, NH, BSZ), 128, ATTN_SMEM>>>(q, k, v, attn);

    split_bf16<<<cgrid, 256>>>(attn, ahi, alo, n4);
    gemm_mma<<<gg, 256, 98304>>>(ahi, alo, wohi, wolo, out);
}

// round 5
// speedup vs baseline: 4.3476x; 1.0052x over previous
#include <cuda_runtime.h>
#include <cuda_bf16.h>
#include <cstdint>
#include <math.h>

#define DIM   4096
#define NH    32
#define HD    128
#define BSZ   2
#define SEQ   2048

// ---------------- scratch (__device__ globals; no allocs allowed) ----------
__device__ float g_q[BSZ*SEQ*DIM];
__device__ float g_k[BSZ*SEQ*DIM];
__device__ float g_v[BSZ*SEQ*DIM];
__device__ float g_attn[BSZ*SEQ*DIM];
__device__ float g_cos[SEQ*(HD/2)];
__device__ float g_sin[SEQ*(HD/2)];

// bf16 split buffers (hi/lo)
__device__ __nv_bfloat16 g_xhi[DIM*DIM],  g_xlo[DIM*DIM];
__device__ __nv_bfloat16 g_wqhi[DIM*DIM], g_wqlo[DIM*DIM];
__device__ __nv_bfloat16 g_wkhi[DIM*DIM], g_wklo[DIM*DIM];
__device__ __nv_bfloat16 g_wvhi[DIM*DIM], g_wvlo[DIM*DIM];
__device__ __nv_bfloat16 g_wohi[DIM*DIM], g_wolo[DIM*DIM];
__device__ __nv_bfloat16 g_ahi[DIM*DIM],  g_alo[DIM*DIM];

// ---------------- base-ISA helpers (compute_103-safe) ----------------------
__device__ __forceinline__ uint32_t smem_u32(const void* p) {
    uint32_t a;
    asm("{ .reg .u64 t; cvta.to.shared.u64 t, %1; cvt.u32.u64 %0, t; }" : "=r"(a) : "l"(p));
    return a;
}
__device__ __forceinline__ void cpa16(uint32_t saddr, const void* g) {
    asm volatile("cp.async.cg.shared.global [%0], [%1], 16;" :: "r"(saddr), "l"(g));
}
__device__ __forceinline__ void ldsm4(uint32_t* r, uint32_t addr) {
    asm volatile("ldmatrix.sync.aligned.m8n8.x4.shared.b16 {%0,%1,%2,%3}, [%4];"
        : "=r"(r[0]), "=r"(r[1]), "=r"(r[2]), "=r"(r[3]) : "r"(addr));
}
__device__ __forceinline__ void mma16816(float* c, const uint32_t* a,
                                         uint32_t b0, uint32_t b1) {
    asm volatile("mma.sync.aligned.m16n8k16.row.col.f32.bf16.bf16.f32 "
        "{%0,%1,%2,%3}, {%4,%5,%6,%7}, {%8,%9}, {%0,%1,%2,%3};"
        : "+f"(c[0]), "+f"(c[1]), "+f"(c[2]), "+f"(c[3])
        : "r"(a[0]), "r"(a[1]), "r"(a[2]), "r"(a[3]), "r"(b0), "r"(b1));
}
__device__ __forceinline__ void mma_tf32(float* c, const uint32_t* a,
                                         uint32_t b0, uint32_t b1) {
    asm volatile("mma.sync.aligned.m16n8k8.row.col.f32.tf32.tf32.f32 "
        "{%0,%1,%2,%3}, {%4,%5,%6,%7}, {%8,%9}, {%0,%1,%2,%3};"
        : "+f"(c[0]), "+f"(c[1]), "+f"(c[2]), "+f"(c[3])
        : "r"(a[0]), "r"(a[1]), "r"(a[2]), "r"(a[3]), "r"(b0), "r"(b1));
}
__device__ __forceinline__ uint32_t to_tf32(float x) {
    uint32_t r;
    asm("cvt.rna.tf32.f32 %0, %1;" : "=r"(r) : "f"(x));
    return r;
}
__device__ __forceinline__ uint32_t sw128(uint32_t off) {
    return off ^ ((off >> 3) & 0x70);
}

// ---------------------------------------------------------------------------
// fp32 -> (bf16 hi, bf16 lo) split, vectorized
// ---------------------------------------------------------------------------
__global__ void split_bf16(const float* __restrict__ in,
                           __nv_bfloat16* __restrict__ hi,
                           __nv_bfloat16* __restrict__ lo, int n4)
{
    int i = blockIdx.x * 256 + threadIdx.x;
    if (i >= n4) return;
    float4 v = ((const float4*)in)[i];
    __nv_bfloat162 h01 = __floats2bfloat162_rn(v.x, v.y);
    __nv_bfloat162 h23 = __floats2bfloat162_rn(v.z, v.w);
    float2 f01 = __bfloat1622float2(h01);
    float2 f23 = __bfloat1622float2(h23);
    __nv_bfloat162 l01 = __floats2bfloat162_rn(v.x - f01.x, v.y - f01.y);
    __nv_bfloat162 l23 = __floats2bfloat162_rn(v.z - f23.x, v.w - f23.y);
    ((__nv_bfloat162*)hi)[2*i]   = h01;
    ((__nv_bfloat162*)hi)[2*i+1] = h23;
    ((__nv_bfloat162*)lo)[2*i]   = l01;
    ((__nv_bfloat162*)lo)[2*i+1] = l23;
}

// ---------------------------------------------------------------------------
// Split-bf16 tensor-core GEMM (NT): C[m,n]=sum_k A[m,k]*W[n,k], 4096^3.
// 128x128 tile, BK=64 (128B rows, SW128), 3-stage cp.async pipeline,
// fragment double-buffering. 8 warps (4Mx2N), warp tile 32x64.
// ---------------------------------------------------------------------------
__global__ void __launch_bounds__(256, 1)
gemm_mma(const __nv_bfloat16* __restrict__ Ahi, const __nv_bfloat16* __restrict__ Alo,
         const __nv_bfloat16* __restrict__ Bhi, const __nv_bfloat16* __restrict__ Blo,
         float* __restrict__ C)
{
    extern __shared__ char sm[];
    const uint32_t s0 = smem_u32(sm);

    const int tid  = threadIdx.x;
    const int wid  = tid >> 5;
    const int lane = tid & 31;
    const int bx = blockIdx.x;
    const int by = blockIdx.y;
    const int warp_m = wid >> 1;   // 0..3 (32 rows each)
    const int warp_n = wid & 1;    // 0..1 (64 cols each)

    float acc[2][8][4];
#pragma unroll
    for (int t = 0; t < 2; t++)
#pragma unroll
        for (int n = 0; n < 8; n++)
#pragma unroll
            for (int j = 0; j < 4; j++) acc[t][n][j] = 0.0f;

    const __nv_bfloat16* gp[4] = {Ahi, Alo, Bhi, Blo};

    // stage: 64KB = 4 mats x 16KB; mat = 128 rows x 128B (64 bf16), SW128
    auto load_stage = [&](int kt, int stage) {
        uint32_t sbase = s0 + stage * 65536;
#pragma unroll
        for (int m = 0; m < 4; m++) {
            const int rowbase = (m < 2 ? by : bx) * 128;
            const __nv_bfloat16* G = gp[m];
#pragma unroll
            for (int i = 0; i < 4; i++) {
                int li = tid + i * 256;           // 0..1023
                int r = li >> 3, c = li & 7;      // row, 16B chunk
                const void* g = G + (size_t)(rowbase + r) * 4096 + kt * 64 + c * 8;
                cpa16(sbase + m * 16384 + sw128((uint32_t)(r * 128 + c * 16)), g);
            }
        }
        asm volatile("cp.async.commit_group;" ::: "memory");
    };

    const int lrow  = (lane & 7) + ((lane >> 3) & 1) * 8;
    const int khalf = (lane >> 4) * 16;

    // double-buffered fragments
    uint32_t ah[2][2][4], al[2][2][4], bh[2][4][4], bl[2][4][4];

    auto ldfr = [&](int buf, int s, uint32_t sbase) {
#pragma unroll
        for (int t = 0; t < 2; t++) {
            uint32_t off = sw128((uint32_t)((warp_m * 32 + t * 16 + lrow) * 128
                                            + khalf + s * 32));
            ldsm4(ah[buf][t], sbase + off);
            ldsm4(al[buf][t], sbase + 16384 + off);
        }
#pragma unroll
        for (int u = 0; u < 4; u++) {
            uint32_t off = sw128((uint32_t)((warp_n * 64 + u * 16 + lrow) * 128
                                            + khalf + s * 32));
            ldsm4(bh[buf][u], sbase + 32768 + off);
            ldsm4(bl[buf][u], sbase + 49152 + off);
        }
    };

    auto do_mma = [&](int buf) {
#pragma unroll
        for (int t = 0; t < 2; t++)
#pragma unroll
            for (int u = 0; u < 4; u++)
#pragma unroll
                for (int j = 0; j < 2; j++) {
                    float* c = acc[t][u * 2 + j];
                    mma16816(c, ah[buf][t], bh[buf][u][j], bh[buf][u][j + 2]);
                    mma16816(c, ah[buf][t], bl[buf][u][j], bl[buf][u][j + 2]);
                    mma16816(c, al[buf][t], bh[buf][u][j], bh[buf][u][j + 2]);
                }
    };

    const int NT = 4096 / 64;   // 64 k-tiles

    load_stage(0, 0);
    load_stage(1, 1);

    for (int kt = 0; kt < NT; kt++) {
        if (kt < NT - 1) asm volatile("cp.async.wait_group 1;" ::: "memory");
        else             asm volatile("cp.async.wait_group 0;" ::: "memory");
        __syncthreads();

        const uint32_t sbase = s0 + (kt % 3) * 65536;
        ldfr(0, 0, sbase);                          // first fragments ASAP
        if (kt + 2 < NT) load_stage(kt + 2, (kt + 2) % 3);

#pragma unroll
        for (int s = 0; s < 4; s++) {
            if (s < 3) ldfr((s + 1) & 1, s + 1, sbase);
            do_mma(s & 1);
        }
    }

    const int g  = lane >> 2;
    const int qc = lane & 3;
#pragma unroll
    for (int t = 0; t < 2; t++) {
        const int row = by * 128 + warp_m * 32 + t * 16 + g;
#pragma unroll
        for (int n = 0; n < 8; n++) {
            const int col = bx * 128 + warp_n * 64 + n * 8 + qc * 2;
            *(float2*)&C[(size_t)row * 4096 + col] =
                make_float2(acc[t][n][0], acc[t][n][1]);
            *(float2*)&C[(size_t)(row + 8) * 4096 + col] =
                make_float2(acc[t][n][2], acc[t][n][3]);
        }
    }
}

// ---------------------------------------------------------------------------
// RoPE
// ---------------------------------------------------------------------------
__global__ void rope_table(float* ct, float* st)
{
    int idx = blockIdx.x * 256 + threadIdx.x;
    if (idx >= SEQ * (HD / 2)) return;
    int s = idx >> 6;
    int j = idx & 63;
    double inv = pow(10000.0, -(double)(2 * j) / 128.0);
    double a = (double)s * inv;
    ct[idx] = (float)cos(a);
    st[idx] = (float)sin(a);
}

__global__ void rope_apply(float* __restrict__ q, float* __restrict__ k,
                           const float* __restrict__ ct, const float* __restrict__ st)
{
    int idx = blockIdx.x * 256 + threadIdx.x;
    if (idx >= BSZ * SEQ * NH * (HD / 2)) return;
    int j = idx & 63;
    int h = (idx >> 6) & 31;
    int s = (idx >> 11) & 2047;
    int b = idx >> 22;
    size_t base = (((size_t)(b * SEQ + s) * NH + h) << 7) + 2 * j;
    float c  = ct[s * 64 + j];
    float sn = st[s * 64 + j];
    float2 xq = *(float2*)&q[base];
    float2 xk = *(float2*)&k[base];
    float2 oq, ok;
    oq.x = xq.x * c - xq.y * sn;
    oq.y = xq.x * sn + xq.y * c;
    ok.x = xk.x * c - xk.y * sn;
    ok.y = xk.x * sn + xk.y * c;
    *(float2*)&q[base] = oq;
    *(float2*)&k[base] = ok;
}

// ---------------------------------------------------------------------------
// Tensor-core causal flash attention (tf32 mma.m16n8k8) — unchanged from R4.
// ---------------------------------------------------------------------------
#define KS_STRIDE 132
#define PS_STRIDE 68
#define ATTN_SMEM ((2*64*KS_STRIDE + 4*16*PS_STRIDE) * 4)

__global__ void __launch_bounds__(128)
attn_tc(const float* __restrict__ Q, const float* __restrict__ Kg,
        const float* __restrict__ Vg, float* __restrict__ O)
{
    extern __shared__ float smf[];
    float* Ks = smf;
    float* Vs = smf + 64 * KS_STRIDE;
    float* Ps = smf + 2 * 64 * KS_STRIDE;

    const int tid  = threadIdx.x;
    const int w    = tid >> 5;
    const int lane = tid & 31;
    const int qt = blockIdx.x;
    const int h  = blockIdx.y;
    const int b  = blockIdx.z;
    const int g  = lane >> 2;
    const int qc = lane & 3;
    float* Pw = Ps + w * 16 * PS_STRIDE;

    const float scale = 0.08838834764831845f;
    const int q0 = qt * 64 + w * 16;

    uint32_t qa[16][4];
    {
        const float* q_r0 = Q + ((size_t)b * SEQ + q0 + g)     * 4096 + h * 128;
        const float* q_r1 = Q + ((size_t)b * SEQ + q0 + g + 8) * 4096 + h * 128;
#pragma unroll
        for (int kc = 0; kc < 16; kc++) {
            qa[kc][0] = to_tf32(q_r0[kc * 8 + qc]     * scale);
            qa[kc][1] = to_tf32(q_r1[kc * 8 + qc]     * scale);
            qa[kc][2] = to_tf32(q_r0[kc * 8 + qc + 4] * scale);
            qa[kc][3] = to_tf32(q_r1[kc * 8 + qc + 4] * scale);
        }
    }

    float o[16][4];
#pragma unroll
    for (int n = 0; n < 16; n++)
#pragma unroll
        for (int j = 0; j < 4; j++) o[n][j] = 0.0f;
    float m0 = -1e30f, m1 = -1e30f, l0 = 0.0f, l1 = 0.0f;

    for (int kt = 0; kt <= qt; kt++) {
        if (kt) __syncthreads();
#pragma unroll
        for (int i = 0; i < 16; i++) {
            int li = tid + i * 128;
            int row = li >> 5, c4 = li & 31;
            size_t gsrc = ((size_t)b * SEQ + kt * 64 + row) * 4096 + h * 128 + c4 * 4;
            float4 kv = *(const float4*)&Kg[gsrc];
            float4 vv = *(const float4*)&Vg[gsrc];
            uint4 kb = make_uint4(to_tf32(kv.x), to_tf32(kv.y), to_tf32(kv.z), to_tf32(kv.w));
            uint4 vb = make_uint4(to_tf32(vv.x), to_tf32(vv.y), to_tf32(vv.z), to_tf32(vv.w));
            *(uint4*)&Ks[row * KS_STRIDE + c4 * 4] = kb;
            *(uint4*)&Vs[row * KS_STRIDE + c4 * 4] = vb;
        }
        __syncthreads();

        float sreg[8][4];
#pragma unroll
        for (int j = 0; j < 8; j++) {
            sreg[j][0] = sreg[j][1] = sreg[j][2] = sreg[j][3] = 0.0f;
            const uint32_t* krow = (const uint32_t*)&Ks[(j * 8 + g) * KS_STRIDE];
#pragma unroll
            for (int kc = 0; kc < 16; kc++)
                mma_tf32(sreg[j], qa[kc], krow[kc * 8 + qc], krow[kc * 8 + qc + 4]);
        }

        if (kt == qt) {
            const int kb = kt * 64;
#pragma unroll
            for (int j = 0; j < 8; j++) {
                int key0 = kb + j * 8 + 2 * qc;
                if (key0     > q0 + g)     sreg[j][0] = -1e30f;
                if (key0 + 1 > q0 + g)     sreg[j][1] = -1e30f;
                if (key0     > q0 + g + 8) sreg[j][2] = -1e30f;
                if (key0 + 1 > q0 + g + 8) sreg[j][3] = -1e30f;
            }
        }

        float mx0 = -1e30f, mx1 = -1e30f;
#pragma unroll
        for (int j = 0; j < 8; j++) {
            mx0 = fmaxf(mx0, fmaxf(sreg[j][0], sreg[j][1]));
            mx1 = fmaxf(mx1, fmaxf(sreg[j][2], sreg[j][3]));
        }
        mx0 = fmaxf(mx0, __shfl_xor_sync(0xffffffffu, mx0, 1));
        mx0 = fmaxf(mx0, __shfl_xor_sync(0xffffffffu, mx0, 2));
        mx1 = fmaxf(mx1, __shfl_xor_sync(0xffffffffu, mx1, 1));
        mx1 = fmaxf(mx1, __shfl_xor_sync(0xffffffffu, mx1, 2));
        float mn0 = fmaxf(m0, mx0), mn1 = fmaxf(m1, mx1);
        float f0 = __expf(m0 - mn0), f1 = __expf(m1 - mn1);
        m0 = mn0; m1 = mn1;

        float sum0 = 0.0f, sum1 = 0.0f;
        uint32_t* PwU = (uint32_t*)Pw;
#pragma unroll
        for (int j = 0; j < 8; j++) {
            float p0 = __expf(sreg[j][0] - mn0);
            float p1 = __expf(sreg[j][1] - mn0);
            float p2 = __expf(sreg[j][2] - mn1);
            float p3 = __expf(sreg[j][3] - mn1);
            sum0 += p0 + p1;
            sum1 += p2 + p3;
            PwU[g * PS_STRIDE       + j * 8 + 2 * qc]     = to_tf32(p0);
            PwU[g * PS_STRIDE       + j * 8 + 2 * qc + 1] = to_tf32(p1);
            PwU[(g + 8) * PS_STRIDE + j * 8 + 2 * qc]     = to_tf32(p2);
            PwU[(g + 8) * PS_STRIDE + j * 8 + 2 * qc + 1] = to_tf32(p3);
        }
        sum0 += __shfl_xor_sync(0xffffffffu, sum0, 1);
        sum0 += __shfl_xor_sync(0xffffffffu, sum0, 2);
        sum1 += __shfl_xor_sync(0xffffffffu, sum1, 1);
        sum1 += __shfl_xor_sync(0xffffffffu, sum1, 2);
        l0 = l0 * f0 + sum0;
        l1 = l1 * f1 + sum1;

#pragma unroll
        for (int n = 0; n < 16; n++) {
            o[n][0] *= f0; o[n][1] *= f0;
            o[n][2] *= f1; o[n][3] *= f1;
        }
        __syncwarp();

        uint32_t pa[8][4];
#pragma unroll
        for (int kc = 0; kc < 8; kc++) {
            pa[kc][0] = PwU[g * PS_STRIDE       + kc * 8 + qc];
            pa[kc][1] = PwU[(g + 8) * PS_STRIDE + kc * 8 + qc];
            pa[kc][2] = PwU[g * PS_STRIDE       + kc * 8 + qc + 4];
            pa[kc][3] = PwU[(g + 8) * PS_STRIDE + kc * 8 + qc + 4];
        }

#pragma unroll
        for (int n = 0; n < 16; n++) {
#pragma unroll
            for (int kc = 0; kc < 8; kc++) {
                uint32_t b0 = ((const uint32_t*)Vs)[(kc * 8 + qc)     * KS_STRIDE + n * 8 + g];
                uint32_t b1 = ((const uint32_t*)Vs)[(kc * 8 + qc + 4) * KS_STRIDE + n * 8 + g];
                mma_tf32(o[n], pa[kc], b0, b1);
            }
        }
    }

    const float inv0 = 1.0f / l0;
    const float inv1 = 1.0f / l1;
    float* o_r0 = O + ((size_t)b * SEQ + q0 + g)     * 4096 + h * 128;
    float* o_r1 = O + ((size_t)b * SEQ + q0 + g + 8) * 4096 + h * 128;
#pragma unroll
    for (int n = 0; n < 16; n++) {
        *(float2*)&o_r0[n * 8 + 2 * qc] = make_float2(o[n][0] * inv0, o[n][1] * inv0);
        *(float2*)&o_r1[n * 8 + 2 * qc] = make_float2(o[n][2] * inv1, o[n][3] * inv1);
    }
}

// ---------------------------------------------------------------------------
extern "C" void kernel_launch(void* const* d_in, const int* in_sizes, int n_in,
                              void* d_out, int out_size)
{
    const float* x = (const float*)d_in[0];
    int off = (n_in >= 6 && in_sizes[1] <= 4) ? 2 : 1;
    const float* wq = (const float*)d_in[off + 0];
    const float* wk = (const float*)d_in[off + 1];
    const float* wv = (const float*)d_in[off + 2];
    const float* wo = (const float*)d_in[off + 3];
    float* out = (float*)d_out;

    float *q, *k, *v, *attn, *ct, *st;
    cudaGetSymbolAddress((void**)&q,    g_q);
    cudaGetSymbolAddress((void**)&k,    g_k);
    cudaGetSymbolAddress((void**)&v,    g_v);
    cudaGetSymbolAddress((void**)&attn, g_attn);
    cudaGetSymbolAddress((void**)&ct,   g_cos);
    cudaGetSymbolAddress((void**)&st,   g_sin);

    __nv_bfloat16 *xhi, *xlo, *wqhi, *wqlo, *wkhi, *wklo, *wvhi, *wvlo, *wohi, *wolo, *ahi, *alo;
    cudaGetSymbolAddress((void**)&xhi,  g_xhi);   cudaGetSymbolAddress((void**)&xlo,  g_xlo);
    cudaGetSymbolAddress((void**)&wqhi, g_wqhi);  cudaGetSymbolAddress((void**)&wqlo, g_wqlo);
    cudaGetSymbolAddress((void**)&wkhi, g_wkhi);  cudaGetSymbolAddress((void**)&wklo, g_wklo);
    cudaGetSymbolAddress((void**)&wvhi, g_wvhi);  cudaGetSymbolAddress((void**)&wvlo, g_wvlo);
    cudaGetSymbolAddress((void**)&wohi, g_wohi);  cudaGetSymbolAddress((void**)&wolo, g_wolo);
    cudaGetSymbolAddress((void**)&ahi,  g_ahi);   cudaGetSymbolAddress((void**)&alo,  g_alo);

    cudaFuncSetAttribute(gemm_mma, cudaFuncAttributeMaxDynamicSharedMemorySize, 196608);
    cudaFuncSetAttribute(attn_tc,  cudaFuncAttributeMaxDynamicSharedMemorySize, ATTN_SMEM);

    const int n4 = DIM * DIM / 4;
    const int cgrid = (n4 + 255) / 256;

    split_bf16<<<cgrid, 256>>>(x,  xhi, xlo, n4);
    split_bf16<<<cgrid, 256>>>(wq, wqhi, wqlo, n4);
    split_bf16<<<cgrid, 256>>>(wk, wkhi, wklo, n4);
    split_bf16<<<cgrid, 256>>>(wv, wvhi, wvlo, n4);
    split_bf16<<<cgrid, 256>>>(wo, wohi, wolo, n4);

    dim3 gg(DIM / 128, DIM / 128);
    gemm_mma<<<gg, 256, 196608>>>(xhi, xlo, wqhi, wqlo, q);
    gemm_mma<<<gg, 256, 196608>>>(xhi, xlo, wkhi, wklo, k);
    gemm_mma<<<gg, 256, 196608>>>(xhi, xlo, wvhi, wvlo, v);

    rope_table<<<(SEQ * (HD / 2) + 255) / 256, 256>>>(ct, st);
    rope_apply<<<(BSZ * SEQ * NH * (HD / 2) + 255) / 256, 256>>>(q, k, ct, st);

    attn_tc<<<dim3(SEQ / 64, NH, BSZ), 128, ATTN_SMEM>>>(q, k, v, attn);

    split_bf16<<<cgrid, 256>>>(attn, ahi, alo, n4);
    gemm_mma<<<gg, 256, 196608>>>(ahi, alo, wohi, wolo, out);
}